// round 12
// baseline (speedup 1.0000x reference)
#include <cuda_runtime.h>
#include <cstdint>

#define LL 4096
#define CC 32
#define LT 16           // l per CTA; warp w owns l = l0+w and l0+w+8
#define THREADS 256     // 8 warps
#define BCH 16          // b rows per chunk (one m16 tile)
#define NCH 4           // chunks per CTA (64 b)
#define BSPLIT 2        // b halves across CTAs

#define XS_U32 (LT * 512)        // 16 planes x (16 b x 32 slots)
#define OPLANE 674               // plane stride (== 2 mod 32: conflict-free gather)
#define OS_FLOATS (LT * OPLANE)  // 10784 floats
#define SMEM_BYTES (XS_U32 * 4 + OS_FLOATS * 4)   // 75904 B

__device__ __forceinline__ uint32_t f2tf32(float f) {
    uint32_t r;
    asm("cvt.rna.tf32.f32 %0, %1;" : "=r"(r) : "f"(f));
    return r;
}

__device__ __forceinline__ void mma_tf32(
    float& d0, float& d1, float& d2, float& d3,
    uint32_t a0, uint32_t a1, uint32_t a2, uint32_t a3,
    uint32_t b0, uint32_t b1,
    float c0, float c1, float c2, float c3) {
    asm("mma.sync.aligned.m16n8k8.row.col.f32.tf32.tf32.f32 "
        "{%0,%1,%2,%3}, {%4,%5,%6,%7}, {%8,%9}, {%10,%11,%12,%13};"
        : "=f"(d0), "=f"(d1), "=f"(d2), "=f"(d3)
        : "r"(a0), "r"(a1), "r"(a2), "r"(a3), "r"(b0), "r"(b1),
          "f"(c0), "f"(c1), "f"(c2), "f"(c3));
}

__global__ void __launch_bounds__(THREADS, 2)
dyna_dec_kernel(const float* __restrict__ x, const float* __restrict__ weight,
                const float* __restrict__ bias, float* __restrict__ out) {
    extern __shared__ __align__(16) char smem[];
    uint32_t* x_s = (uint32_t*)smem;
    float*    o_s = (float*)(smem + XS_U32 * 4);

    const int tid  = threadIdx.x;
    const int w    = tid >> 5;
    const int lane = tid & 31;
    const int q    = lane & 3;       // mma k-in-tile
    const int p    = lane >> 2;      // mma row/col group
    const int b0   = blockIdx.x * (BCH * NCH);   // b-split fastest: weight L2 reuse
    const int l0   = blockIdx.y * LT;

    // ---- B fragments + bias for this warp's two l positions ----
    uint32_t bf[2][4][4][2];
    float    bb[2][4][2];
    #pragma unroll
    for (int li = 0; li < 2; li++) {
        const int lg = l0 + w + 8 * li;
        const float* wp = weight + (size_t)lg * CC * CC;
        #pragma unroll
        for (int nt = 0; nt < 4; nt++) {
            #pragma unroll
            for (int kt = 0; kt < 4; kt++) {
                bf[li][kt][nt][0] = f2tf32(__ldg(wp + (8 * kt + q) * CC + 8 * nt + p));
                bf[li][kt][nt][1] = f2tf32(__ldg(wp + (8 * kt + q + 4) * CC + 8 * nt + p));
            }
            float2 bv = *(const float2*)(bias + (size_t)lg * CC + 8 * nt + 2 * q);
            bb[li][nt][0] = bv.x;
            bb[li][nt][1] = bv.y;
        }
    }

    for (int ch = 0; ch < NCH; ch++) {
        const int cb = b0 + ch * BCH;

        // ---- stage: rows stride-4 in c, 4 l-segs per row; conflict-free STS ----
        #pragma unroll
        for (int it = 0; it < 8; it++) {
            int combo = it * 8 + w;              // 0..63
            int bl = combo >> 2, qq = combo & 3;
            int cc = lane >> 2, s = lane & 3;
            int c  = 4 * cc + qq;
            float4 v = *(const float4*)(x + ((size_t)((cb + bl) * CC + c)) * LL + l0 + 4 * s);
            // perm(c)=8qq+cc; + row rot 4(bl&7); + seg rot 8s (= 8*(plane>>2))
            int slot = (8 * qq + cc + 4 * (bl & 7) + 8 * s) & 31;
            uint32_t* dst = x_s + (4 * s) * 512 + bl * 32 + slot;
            dst[0]    = f2tf32(v.x);
            dst[512]  = f2tf32(v.y);
            dst[1024] = f2tf32(v.z);
            dst[1536] = f2tf32(v.w);
        }
        __syncthreads();

        // ---- compute: 2 l per warp, 4x LDS.128 + 16 mma each ----
        #pragma unroll
        for (int li = 0; li < 2; li++) {
            const int l = w + 8 * li;
            const uint32_t* xp = x_s + l * 512;
            const int rotc = 8 * (l >> 2);
            const int o1 = (8 * q + 4 * p + rotc) & 31;
            const int o2 = (8 * q + 4 * p + 4 + rotc) & 31;
            uint4 v00 = *(const uint4*)(xp + p * 32 + o1);
            uint4 v01 = *(const uint4*)(xp + p * 32 + o2);
            uint4 v10 = *(const uint4*)(xp + (p + 8) * 32 + o1);
            uint4 v11 = *(const uint4*)(xp + (p + 8) * 32 + o2);

            float acc[4][4];
            #pragma unroll
            for (int nt = 0; nt < 4; nt++) {
                acc[nt][0] = bb[li][nt][0]; acc[nt][1] = bb[li][nt][1];
                acc[nt][2] = bb[li][nt][0]; acc[nt][3] = bb[li][nt][1];
            }
            #pragma unroll
            for (int nt = 0; nt < 4; nt++) {
                mma_tf32(acc[nt][0], acc[nt][1], acc[nt][2], acc[nt][3],
                         v00.x, v10.x, v00.y, v10.y,
                         bf[li][0][nt][0], bf[li][0][nt][1],
                         acc[nt][0], acc[nt][1], acc[nt][2], acc[nt][3]);
                mma_tf32(acc[nt][0], acc[nt][1], acc[nt][2], acc[nt][3],
                         v00.z, v10.z, v00.w, v10.w,
                         bf[li][1][nt][0], bf[li][1][nt][1],
                         acc[nt][0], acc[nt][1], acc[nt][2], acc[nt][3]);
                mma_tf32(acc[nt][0], acc[nt][1], acc[nt][2], acc[nt][3],
                         v01.x, v11.x, v01.y, v11.y,
                         bf[li][2][nt][0], bf[li][2][nt][1],
                         acc[nt][0], acc[nt][1], acc[nt][2], acc[nt][3]);
                mma_tf32(acc[nt][0], acc[nt][1], acc[nt][2], acc[nt][3],
                         v01.z, v11.z, v01.w, v11.w,
                         bf[li][3][nt][0], bf[li][3][nt][1],
                         acc[nt][0], acc[nt][1], acc[nt][2], acc[nt][3]);
            }
            // D -> o_s[plane l][d*21 + bl]
            float* op = o_s + l * OPLANE;
            #pragma unroll
            for (int nt = 0; nt < 4; nt++) {
                int d = 8 * nt + 2 * q;
                op[d * 21 + p]           = acc[nt][0];
                op[(d + 1) * 21 + p]     = acc[nt][1];
                op[d * 21 + p + 8]       = acc[nt][2];
                op[(d + 1) * 21 + p + 8] = acc[nt][3];
            }
        }
        __syncthreads();

        // ---- out-pass: conflict-free scalar gather (8s2+21dd distinct), STG.128 ----
        #pragma unroll
        for (int it = 0; it < 8; it++) {
            int combo = it * 8 + w;              // 0..63
            int bl = combo & 15, dblk = combo >> 4;
            int dd = lane & 7, s2 = lane >> 3;
            int d  = dblk * 8 + dd;
            const float* src = o_s + (4 * s2) * OPLANE + d * 21 + bl;
            float4 v;
            v.x = src[0 * OPLANE];
            v.y = src[1 * OPLANE];
            v.z = src[2 * OPLANE];
            v.w = src[3 * OPLANE];
            *(float4*)(out + ((size_t)((cb + bl) * CC + d)) * LL + l0 + 4 * s2) = v;
        }
        // stage(ch+1) writes x_s only (disjoint from o_s); compute(ch+1)'s o_s
        // writes are fenced by the stage-end sync. No third barrier needed.
    }
}

extern "C" void kernel_launch(void* const* d_in, const int* in_sizes, int n_in,
                              void* d_out, int out_size) {
    const float* x      = (const float*)d_in[0];
    // d_in[1] = px, unused by the reference
    const float* weight = (const float*)d_in[2];
    const float* bias   = (const float*)d_in[3];
    float* out          = (float*)d_out;

    cudaFuncSetAttribute(dyna_dec_kernel, cudaFuncAttributeMaxDynamicSharedMemorySize,
                         SMEM_BYTES);
    dim3 grid(BSPLIT, LL / LT);   // (2, 256): weight-sharing siblings adjacent
    dim3 block(THREADS);
    dyna_dec_kernel<<<grid, block, SMEM_BYTES>>>(x, weight, bias, out);
}